// round 16
// baseline (speedup 1.0000x reference)
#include <cuda_runtime.h>
#include <math.h>

#define NATOMS 4096
#define KX 14
#define KY 15
#define KZ 16
#define NGRID (KX*KY*KZ)          /* 3360 */
#define KYZ (KY*KZ)               /* 240 */
#define ALPHAF 4.985823141035867f
#define ALPHAD 4.985823141035867
#define COULOMB 138.935
#define CUT2 0.25f
#define NBLK 148                  /* one block per SM: all resident */
#define NTHR 1024
#define NMESH 14                  /* mesh pipeline blocks (one per gx plane) */
#define NDIRB (NBLK - NMESH)      /* 134 direct blocks */
#define CDIM 6                    /* 6x6x6 cell grid, cell >= cutoff per axis */
#define NCELL 216
#define CAP 64                    /* slots per cell (avg 19; P(>64) ~ 1e-15) */

// -------- device scratch (static, allocation-free) --------
__device__ float  g_grid[NGRID];
__device__ float2 g_cy[NGRID];
__device__ float4 g_cellbuf[NCELL * CAP];
__device__ int    g_ccnt[NCELL];       // zero-init; re-zeroed by combiner
__device__ double g_edir, g_erec, g_q2;
__device__ double g_V;
__device__ unsigned int g_done;        // zero-init; reset by combiner
__device__ unsigned int g_ticket;      // cell ticket; reset by combiner
__device__ unsigned int g_mcount, g_mgen;   // mesh barrier (monotonic gen)
__device__ unsigned int g_dcount, g_dgen;   // direct barrier (monotonic gen)
__device__ volatile unsigned int g_binflag; // level flag; reset by combiner

// -------- subset barriers (blocks all resident) --------
__device__ __forceinline__ void meshbar() {
    __syncthreads();
    if (threadIdx.x == 0) {
        __threadfence();
        unsigned gen = *(volatile unsigned*)&g_mgen;
        if (atomicAdd(&g_mcount, 1u) == NMESH - 1) {
            *(volatile unsigned*)&g_mcount = 0;
            __threadfence();
            *(volatile unsigned*)&g_mgen = gen + 1;
        } else {
            while (*(volatile unsigned*)&g_mgen == gen) __nanosleep(32);
        }
        __threadfence();
    }
    __syncthreads();
}
__device__ __forceinline__ void dirbar() {
    __syncthreads();
    if (threadIdx.x == 0) {
        __threadfence();
        unsigned gen = *(volatile unsigned*)&g_dgen;
        if (atomicAdd(&g_dcount, 1u) == NDIRB - 1) {
            *(volatile unsigned*)&g_dcount = 0;
            __threadfence();
            *(volatile unsigned*)&g_dgen = gen + 1;
        } else {
            while (*(volatile unsigned*)&g_dgen == gen) __nanosleep(32);
        }
        __threadfence();
    }
    __syncthreads();
}

// -------- fast erfc (Abramowitz-Stegun 7.1.26, abs err <= 1.5e-7) --------
__device__ __forceinline__ float erfc_fast(float x) {
    float t = __fdividef(1.0f, fmaf(0.3275911f, x, 1.0f));
    float p = fmaf(fmaf(fmaf(fmaf(1.061405429f, t, -1.453152027f),
                             t, 1.421413741f),
                        t, -0.284496736f),
                   t, 0.254829592f) * t;
    return p * __expf(-x * x);
}

// -------- order-5 cardinal B-spline: d[k] = M5(w+k), w in [0,1) --------
__device__ __forceinline__ void bspline5(float w, float d[5]) {
    float b2_0 = w, b2_1 = 1.0f - w;
    float b3_0 = 0.5f * w * b2_0;
    float b3_1 = 0.5f * ((w + 1.0f) * b2_1 + (2.0f - w) * b2_0);
    float b3_2 = 0.5f * (1.0f - w) * b2_1;
    const float i3 = 1.0f / 3.0f;
    float b4_0 = i3 * w * b3_0;
    float b4_1 = i3 * ((w + 1.0f) * b3_1 + (3.0f - w) * b3_0);
    float b4_2 = i3 * ((w + 2.0f) * b3_2 + (2.0f - w) * b3_1);
    float b4_3 = i3 * (1.0f - w) * b3_2;
    d[0] = 0.25f * w * b4_0;
    d[1] = 0.25f * ((w + 1.0f) * b4_1 + (4.0f - w) * b4_0);
    d[2] = 0.25f * ((w + 2.0f) * b4_2 + (3.0f - w) * b4_1);
    d[3] = 0.25f * ((w + 3.0f) * b4_3 + (2.0f - w) * b4_2);
    d[4] = 0.25f * (1.0f - w) * b4_3;
}

__global__ void __launch_bounds__(NTHR) k_all(const float* __restrict__ pos,
                                              const float* __restrict__ chg,
                                              const float* __restrict__ box,
                                              float* __restrict__ out) {
    __shared__ float  s_twc[45], s_tws[45], s_bmod[45];
    __shared__ float  s_inv[9];
    __shared__ float  s_plane[240];
    __shared__ float  s_czr[240], s_czi[240];
    __shared__ float4 s_nb[27 * CAP];      // 27.6 KB neighborhood buffer
    __shared__ int    s_cid[27], s_cnt[27], s_off[28];
    __shared__ float  sred[32];
    __shared__ int    s_tile;

    const int gid = blockIdx.x;
    const int tid = threadIdx.x;
    const int lane = tid & 31;
    const int wid = tid >> 5;

    if (gid < NMESH) {
        // ================= MESH PIPELINE (blocks 0..13) =================
        const int m = gid;   // gx plane owned by this block

        if (tid < 45) {
            int K, mm;
            if      (tid < KX)      { K = KX; mm = tid; }
            else if (tid < KX + KY) { K = KY; mm = tid - KX; }
            else                    { K = KZ; mm = tid - KX - KY; }
            float s, c;
            sincospif(2.0f * (float)mm / (float)K, &s, &c);
            s_twc[tid] = c; s_tws[tid] = s;
            const float Mv[4] = {1.0f/24.0f, 11.0f/24.0f, 11.0f/24.0f, 1.0f/24.0f};
            float dr = 0.0f, di = 0.0f;
            #pragma unroll
            for (int k = 0; k < 4; k++) {
                int p = (mm * k) % K;
                float ss, cc;
                sincospif(2.0f * (float)p / (float)K, &ss, &cc);
                dr += Mv[k] * cc; di += Mv[k] * ss;
            }
            float d2 = dr*dr + di*di;
            s_bmod[tid] = (d2 < 1e-7f) ? 0.0f : 1.0f / d2;
        }
        if (tid == 64) {
            double b00 = box[0], b01 = box[1], b02 = box[2];
            double b10 = box[3], b11 = box[4], b12 = box[5];
            double b20 = box[6], b21 = box[7], b22 = box[8];
            double c00 =  (b11*b22 - b12*b21);
            double c01 = -(b10*b22 - b12*b20);
            double c02 =  (b10*b21 - b11*b20);
            double det = b00*c00 + b01*c01 + b02*c02;
            double id = 1.0 / det;
            s_inv[0] = (float)(c00 * id);
            s_inv[1] = (float)(-(b01*b22 - b02*b21) * id);
            s_inv[2] = (float)( (b01*b12 - b02*b11) * id);
            s_inv[3] = (float)(c01 * id);
            s_inv[4] = (float)( (b00*b22 - b02*b20) * id);
            s_inv[5] = (float)(-(b00*b12 - b02*b10) * id);
            s_inv[6] = (float)(c02 * id);
            s_inv[7] = (float)(-(b00*b21 - b01*b20) * id);
            s_inv[8] = (float)( (b00*b11 - b01*b10) * id);
            if (m == 0) g_V = fabs(det);
        }
        if (tid < KYZ) g_grid[m * KYZ + tid] = 0.0f;
        meshbar();   // grid zeroed, tables local

        // ---- spread + q^2 ----
        {
            float q2c = 0.0f;
            for (int idx = tid; idx < 293 * 5; idx += NTHR) {
                int k  = idx / 5;
                int aa = idx - 5 * k;
                int a  = m + NMESH * k;
                if (a >= NATOMS) break;
                float q = chg[a];
                if (aa == 0) q2c += q * q;
                float px = pos[3*a], py = pos[3*a+1], pz = pos[3*a+2];
                const int Ks[3] = {KX, KY, KZ};
                float wts[3][5];
                int   idxg[3][5];
                #pragma unroll
                for (int d = 0; d < 3; d++) {
                    float f = px*s_inv[0+d] + py*s_inv[3+d] + pz*s_inv[6+d];
                    f -= floorf(f);
                    if (f >= 1.0f) f = 0.0f;
                    float u  = f * (float)Ks[d];
                    float fl = floorf(u);
                    int base = (int)fl;
                    if (base >= Ks[d]) { base = Ks[d] - 1; fl = (float)base; }
                    float w = u - fl;
                    bspline5(w, wts[d]);
                    #pragma unroll
                    for (int kk = 0; kk < 5; kk++) {
                        int ii = base - kk;
                        if (ii < 0) ii += Ks[d];
                        idxg[d][kk] = ii;
                    }
                }
                int offx = idxg[0][aa] * KYZ;
                float wx = q * wts[0][aa];
                #pragma unroll
                for (int bb = 0; bb < 5; bb++) {
                    float wab = wx * wts[1][bb];
                    int off = offx + idxg[1][bb] * KZ;
                    #pragma unroll
                    for (int cc = 0; cc < 5; cc++)
                        atomicAdd(&g_grid[off + idxg[2][cc]], wab * wts[2][cc]);
                }
            }
            #pragma unroll
            for (int o = 16; o; o >>= 1) q2c += __shfl_xor_sync(0xffffffffu, q2c, o);
            if (lane == 0) sred[wid] = q2c;
            __syncthreads();
            if (tid == 0) {
                float s = 0.0f;
                #pragma unroll
                for (int w = 0; w < 32; w++) s += sred[w];
                if (s != 0.0f) atomicAdd(&g_q2, (double)s);
            }
        }
        meshbar();   // full mesh ready

        // ---- z-DFT + y-DFT of own plane ----
        if (tid < KYZ) s_plane[tid] = g_grid[m * KYZ + tid];
        __syncthreads();
        if (tid < KYZ) {
            int gy = tid >> 4, mz = tid & 15;
            float fr = 0.0f, fi = 0.0f;
            #pragma unroll
            for (int gz = 0; gz < KZ; gz++) {
                int p = (mz * gz) & (KZ - 1);
                float v = s_plane[(gy << 4) + gz];
                fr = fmaf(v,  s_twc[29 + p], fr);
                fi = fmaf(v, -s_tws[29 + p], fi);
            }
            s_czr[tid] = fr; s_czi[tid] = fi;
        }
        __syncthreads();
        if (tid < KYZ) {
            int my = tid >> 4, mz = tid & 15;
            float fr = 0.0f, fi = 0.0f;
            #pragma unroll
            for (int gy = 0; gy < KY; gy++) {
                float ar = s_czr[(gy << 4) + mz], ai = s_czi[(gy << 4) + mz];
                int p = (my * gy) % KY;
                float c = s_twc[14 + p], s = s_tws[14 + p];
                fr += ar * c + ai * s;
                fi += ai * c - ar * s;
            }
            g_cy[m * KYZ + tid] = make_float2(fr, fi);
        }
        meshbar();   // all planes' cy ready

        // ---- x-DFT + green/B reduce ----
        {
            float contrib = 0.0f;
            if (tid < KYZ) {
                int mx = m, my = tid >> 4, mz = tid & 15;
                float fr = 0.0f, fi = 0.0f;
                #pragma unroll
                for (int gx = 0; gx < KX; gx++) {
                    float2 cv = g_cy[gx * KYZ + tid];
                    int p = (mx * gx) % KX;
                    float c = s_twc[p], s = s_tws[p];
                    fr += cv.x * c + cv.y * s;
                    fi += cv.y * c - cv.x * s;
                }
                int smx = (mx <= (KX - 1) / 2) ? mx : mx - KX;
                int smy = (my <= (KY - 1) / 2) ? my : my - KY;
                int smz = (mz <= (KZ - 1) / 2) ? mz : mz - KZ;
                float fx = (float)smx, fy = (float)smy, fz = (float)smz;
                float mv0 = fx*s_inv[0] + fy*s_inv[1] + fz*s_inv[2];
                float mv1 = fx*s_inv[3] + fy*s_inv[4] + fz*s_inv[5];
                float mv2 = fx*s_inv[6] + fy*s_inv[7] + fz*s_inv[8];
                float m2 = mv0*mv0 + mv1*mv1 + mv2*mv2;
                if (m2 > 0.0f) {
                    const float pi2_over_a2 = (float)(9.869604401089358 / (ALPHAD * ALPHAD));
                    float green = __expf(-pi2_over_a2 * m2) / m2;
                    float B = s_bmod[mx] * s_bmod[14 + my] * s_bmod[29 + mz];
                    contrib = green * B * (fr*fr + fi*fi);
                }
            }
            #pragma unroll
            for (int o = 16; o; o >>= 1) contrib += __shfl_xor_sync(0xffffffffu, contrib, o);
            if (lane == 0) sred[wid] = contrib;
            __syncthreads();
            if (tid == 0) {
                float s = 0.0f;
                #pragma unroll
                for (int w = 0; w < 32; w++) s += sred[w];
                if (s != 0.0f) atomicAdd(&g_erec, (double)s);
            }
        }
        // ---- wait for binning before joining the cell pool ----
        if (tid == 0) {
            while (g_binflag == 0u) __nanosleep(64);
            __threadfence();
        }
        __syncthreads();
    } else {
        // ================= DIRECT BLOCKS: bin atoms into cells =================
        {
            int a = (gid - NMESH) * NTHR + tid;    // blocks 14..17 cover all atoms
            if (a < NATOMS) {
                float px = pos[3*a], py = pos[3*a+1], pz = pos[3*a+2];
                float q = chg[a];
                float Lx = box[0], Ly = box[4], Lz = box[8];
                int cx = (int)(px * (float)CDIM / Lx); cx = min(CDIM-1, max(0, cx));
                int cy = (int)(py * (float)CDIM / Ly); cy = min(CDIM-1, max(0, cy));
                int cz = (int)(pz * (float)CDIM / Lz); cz = min(CDIM-1, max(0, cz));
                int cid = (cx * CDIM + cy) * CDIM + cz;
                int slot = atomicAdd(&g_ccnt[cid], 1);
                if (slot < CAP) g_cellbuf[cid * CAP + slot] = make_float4(px, py, pz, q);
            }
        }
        dirbar();                                   // all bins visible
        if (gid == NMESH && tid == 0) { __threadfence(); g_binflag = 1u; }
    }

    // ================= DIRECT SPACE: cell ticket pool (all blocks) =================
    {
        float Lx = box[0], Ly = box[4], Lz = box[8];
        float accTot = 0.0f;

        for (;;) {
            __syncthreads();                        // previous cell's smem reads done
            if (tid == 0) s_tile = (int)atomicAdd(&g_ticket, 1u);
            __syncthreads();
            int c = s_tile;
            if (c >= NCELL) break;

            // decode home cell, compute 27 neighbor cells
            if (tid < 27) {
                int hx = c / (CDIM * CDIM), rem = c % (CDIM * CDIM);
                int hy = rem / CDIM, hz = rem % CDIM;
                int ox = tid / 9 - 1, oy = (tid / 3) % 3 - 1, oz = tid % 3 - 1;
                int cx = hx + ox; if (cx < 0) cx += CDIM; if (cx >= CDIM) cx -= CDIM;
                int cy = hy + oy; if (cy < 0) cy += CDIM; if (cy >= CDIM) cy -= CDIM;
                int cz = hz + oz; if (cz < 0) cz += CDIM; if (cz >= CDIM) cz -= CDIM;
                int cid = (cx * CDIM + cy) * CDIM + cz;
                s_cid[tid] = cid;
                s_cnt[tid] = min(g_ccnt[cid], CAP);
            }
            __syncthreads();
            if (tid == 0) {
                int run = 0;
                #pragma unroll
                for (int k = 0; k < 27; k++) { s_off[k] = run; run += s_cnt[k]; }
                s_off[27] = run;
            }
            __syncthreads();

            // gather neighborhood compactly into smem
            for (int idx = tid; idx < 27 * CAP; idx += NTHR) {
                int k = idx >> 6;      // / CAP
                int s = idx & (CAP - 1);
                if (s < s_cnt[k]) s_nb[s_off[k] + s] = g_cellbuf[s_cid[k] * CAP + s];
            }
            __syncthreads();

            // pair loop: warp = home atom (offset 13 = home cell), lanes stride neighborhood
            int cnt_h = s_cnt[13], base_h = s_off[13], total = s_off[27];
            for (int ih = wid; ih < cnt_h; ih += 32) {
                float4 me = s_nb[base_h + ih];
                for (int j = lane; j < total; j += 32) {
                    float4 p = s_nb[j];
                    float dx = fabsf(me.x - p.x); dx = fminf(dx, Lx - dx);
                    float dy = fabsf(me.y - p.y); dy = fminf(dy, Ly - dy);
                    float dz = fabsf(me.z - p.z); dz = fminf(dz, Lz - dz);
                    float r2 = fmaf(dx, dx, fmaf(dy, dy, dz * dz));
                    float rinv = rsqrtf(r2);
                    float x = ALPHAF * r2 * rinv;
                    float e = me.w * p.w * erfc_fast(x) * rinv;
                    bool hit = (r2 < CUT2) && (r2 > 0.0f);   // r2==0 <=> self
                    accTot += hit ? e : 0.0f;
                }
            }
        }
        // ordered pairs counted once here, twice across home cells => full matrix
        #pragma unroll
        for (int o = 16; o; o >>= 1) accTot += __shfl_xor_sync(0xffffffffu, accTot, o);
        if (lane == 0) sred[wid] = accTot;
        __syncthreads();
        if (tid == 0) {
            float s = 0.0f;
            #pragma unroll
            for (int w = 0; w < 32; w++) s += sred[w];
            if (s != 0.0f) atomicAdd(&g_edir, (double)s);
        }
    }

    // ================= arrival counter: last block combines + cleans =================
    __syncthreads();
    if (tid == 0) {
        __threadfence();
        unsigned done = atomicAdd(&g_done, 1u);
        if (done == NBLK - 1) {
            __threadfence();             // acquire all blocks' writes
            const double SQRT_PI = 1.7724538509055159;
            double edir  = 0.5 * COULOMB * g_edir;
            double erec  = COULOMB / (2.0 * 3.141592653589793 * g_V) * g_erec;
            double eself = -COULOMB * ALPHAD / SQRT_PI * g_q2;
            out[0] = (float)(edir - (erec + eself));
            // leave-clean for next graph replay
            g_edir = 0.0; g_erec = 0.0; g_q2 = 0.0;
            for (int k = 0; k < NCELL; k++) g_ccnt[k] = 0;
            g_binflag = 0u;
            *(volatile unsigned*)&g_ticket = 0;
            __threadfence();
            *(volatile unsigned*)&g_done = 0;
        }
    }
}

extern "C" void kernel_launch(void* const* d_in, const int* in_sizes, int n_in,
                              void* d_out, int out_size) {
    int ip = 0, ic = 1, ib = 2;
    for (int k = 0; k < n_in; k++) {
        if (in_sizes[k] == NATOMS * 3) ip = k;
        else if (in_sizes[k] == NATOMS) ic = k;
        else if (in_sizes[k] == 9)      ib = k;
    }
    const float* pos = (const float*)d_in[ip];
    const float* chg = (const float*)d_in[ic];
    const float* box = (const float*)d_in[ib];
    float* out = (float*)d_out;

    k_all<<<NBLK, NTHR>>>(pos, chg, box, out);
}

// round 17
// speedup vs baseline: 1.2636x; 1.2636x over previous
#include <cuda_runtime.h>
#include <math.h>

#define NATOMS 4096
#define KX 14
#define KY 15
#define KZ 16
#define NGRID (KX*KY*KZ)          /* 3360 */
#define KYZ (KY*KZ)               /* 240 */
#define ALPHAF 4.985823141035867f
#define ALPHAD 4.985823141035867
#define COULOMB 138.935
#define CUT2 0.25f
#define NBLK 148                  /* one block per SM: all resident */
#define NTHR 1024
#define NMESH 14                  /* mesh pipeline blocks (one per gx plane) */
#define NDIRB (NBLK - NMESH)      /* 134 direct blocks */
#define NDWARP (NDIRB * 32)       /* 4288 direct warps */
#define CDIM 6                    /* 6x6x6 cells, cell >= cutoff per axis */
#define NCELL 216
#define NTASK (NCELL * 27)        /* 5832 warp tasks */
#define CAP 64                    /* slots per cell (avg 19; P(>64) ~ 1e-15) */

// -------- device scratch (static, allocation-free) --------
__device__ float  g_grid[NGRID];
__device__ float2 g_cy[NGRID];
__device__ float4 g_cellbuf[NCELL * CAP];
__device__ int    g_ccnt[NCELL];       // zeroed by block NMESH at replay start
__device__ double g_edir, g_erec, g_q2;
__device__ double g_V;
__device__ unsigned int g_done;        // zero-init; reset by combiner
__device__ unsigned int g_mcount, g_mgen;   // mesh barrier (monotonic gen)
__device__ unsigned int g_dcount, g_dgen;   // direct barrier (monotonic gen)

// -------- subset barriers (blocks all resident) --------
__device__ __forceinline__ void meshbar() {
    __syncthreads();
    if (threadIdx.x == 0) {
        __threadfence();
        unsigned gen = *(volatile unsigned*)&g_mgen;
        if (atomicAdd(&g_mcount, 1u) == NMESH - 1) {
            *(volatile unsigned*)&g_mcount = 0;
            __threadfence();
            *(volatile unsigned*)&g_mgen = gen + 1;
        } else {
            while (*(volatile unsigned*)&g_mgen == gen) __nanosleep(32);
        }
        __threadfence();
    }
    __syncthreads();
}
__device__ __forceinline__ void dirbar() {
    __syncthreads();
    if (threadIdx.x == 0) {
        __threadfence();
        unsigned gen = *(volatile unsigned*)&g_dgen;
        if (atomicAdd(&g_dcount, 1u) == NDIRB - 1) {
            *(volatile unsigned*)&g_dcount = 0;
            __threadfence();
            *(volatile unsigned*)&g_dgen = gen + 1;
        } else {
            while (*(volatile unsigned*)&g_dgen == gen) __nanosleep(32);
        }
        __threadfence();
    }
    __syncthreads();
}

// -------- fast erfc (Abramowitz-Stegun 7.1.26, abs err <= 1.5e-7) --------
__device__ __forceinline__ float erfc_fast(float x) {
    float t = __fdividef(1.0f, fmaf(0.3275911f, x, 1.0f));
    float p = fmaf(fmaf(fmaf(fmaf(1.061405429f, t, -1.453152027f),
                             t, 1.421413741f),
                        t, -0.284496736f),
                   t, 0.254829592f) * t;
    return p * __expf(-x * x);
}

// -------- order-5 cardinal B-spline: d[k] = M5(w+k), w in [0,1) --------
__device__ __forceinline__ void bspline5(float w, float d[5]) {
    float b2_0 = w, b2_1 = 1.0f - w;
    float b3_0 = 0.5f * w * b2_0;
    float b3_1 = 0.5f * ((w + 1.0f) * b2_1 + (2.0f - w) * b2_0);
    float b3_2 = 0.5f * (1.0f - w) * b2_1;
    const float i3 = 1.0f / 3.0f;
    float b4_0 = i3 * w * b3_0;
    float b4_1 = i3 * ((w + 1.0f) * b3_1 + (3.0f - w) * b3_0);
    float b4_2 = i3 * ((w + 2.0f) * b3_2 + (2.0f - w) * b3_1);
    float b4_3 = i3 * (1.0f - w) * b3_2;
    d[0] = 0.25f * w * b4_0;
    d[1] = 0.25f * ((w + 1.0f) * b4_1 + (4.0f - w) * b4_0);
    d[2] = 0.25f * ((w + 2.0f) * b4_2 + (3.0f - w) * b4_1);
    d[3] = 0.25f * ((w + 3.0f) * b4_3 + (2.0f - w) * b4_2);
    d[4] = 0.25f * (1.0f - w) * b4_3;
}

__global__ void __launch_bounds__(NTHR) k_all(const float* __restrict__ pos,
                                              const float* __restrict__ chg,
                                              const float* __restrict__ box,
                                              float* __restrict__ out) {
    __shared__ float  s_twc[45], s_tws[45], s_bmod[45];
    __shared__ float  s_inv[9];
    __shared__ float  s_plane[240];
    __shared__ float  s_czr[240], s_czi[240];
    __shared__ float  sred[32];

    const int gid = blockIdx.x;
    const int tid = threadIdx.x;
    const int lane = tid & 31;
    const int wid = tid >> 5;

    if (gid < NMESH) {
        // ================= MESH PIPELINE (blocks 0..13) =================
        const int m = gid;   // gx plane owned by this block

        if (tid < 45) {
            int K, mm;
            if      (tid < KX)      { K = KX; mm = tid; }
            else if (tid < KX + KY) { K = KY; mm = tid - KX; }
            else                    { K = KZ; mm = tid - KX - KY; }
            float s, c;
            sincospif(2.0f * (float)mm / (float)K, &s, &c);
            s_twc[tid] = c; s_tws[tid] = s;
            const float Mv[4] = {1.0f/24.0f, 11.0f/24.0f, 11.0f/24.0f, 1.0f/24.0f};
            float dr = 0.0f, di = 0.0f;
            #pragma unroll
            for (int k = 0; k < 4; k++) {
                int p = (mm * k) % K;
                float ss, cc;
                sincospif(2.0f * (float)p / (float)K, &ss, &cc);
                dr += Mv[k] * cc; di += Mv[k] * ss;
            }
            float d2 = dr*dr + di*di;
            s_bmod[tid] = (d2 < 1e-7f) ? 0.0f : 1.0f / d2;
        }
        if (tid == 64) {
            double b00 = box[0], b01 = box[1], b02 = box[2];
            double b10 = box[3], b11 = box[4], b12 = box[5];
            double b20 = box[6], b21 = box[7], b22 = box[8];
            double c00 =  (b11*b22 - b12*b21);
            double c01 = -(b10*b22 - b12*b20);
            double c02 =  (b10*b21 - b11*b20);
            double det = b00*c00 + b01*c01 + b02*c02;
            double id = 1.0 / det;
            s_inv[0] = (float)(c00 * id);
            s_inv[1] = (float)(-(b01*b22 - b02*b21) * id);
            s_inv[2] = (float)( (b01*b12 - b02*b11) * id);
            s_inv[3] = (float)(c01 * id);
            s_inv[4] = (float)( (b00*b22 - b02*b20) * id);
            s_inv[5] = (float)(-(b00*b12 - b02*b10) * id);
            s_inv[6] = (float)(c02 * id);
            s_inv[7] = (float)(-(b00*b21 - b01*b20) * id);
            s_inv[8] = (float)( (b00*b11 - b01*b10) * id);
            if (m == 0) g_V = fabs(det);
        }
        if (tid < KYZ) g_grid[m * KYZ + tid] = 0.0f;
        meshbar();   // grid zeroed, tables local

        // ---- spread + q^2 ----
        {
            float q2c = 0.0f;
            for (int idx = tid; idx < 293 * 5; idx += NTHR) {
                int k  = idx / 5;
                int aa = idx - 5 * k;
                int a  = m + NMESH * k;
                if (a >= NATOMS) break;
                float q = chg[a];
                if (aa == 0) q2c += q * q;
                float px = pos[3*a], py = pos[3*a+1], pz = pos[3*a+2];
                const int Ks[3] = {KX, KY, KZ};
                float wts[3][5];
                int   idxg[3][5];
                #pragma unroll
                for (int d = 0; d < 3; d++) {
                    float f = px*s_inv[0+d] + py*s_inv[3+d] + pz*s_inv[6+d];
                    f -= floorf(f);
                    if (f >= 1.0f) f = 0.0f;
                    float u  = f * (float)Ks[d];
                    float fl = floorf(u);
                    int base = (int)fl;
                    if (base >= Ks[d]) { base = Ks[d] - 1; fl = (float)base; }
                    float w = u - fl;
                    bspline5(w, wts[d]);
                    #pragma unroll
                    for (int kk = 0; kk < 5; kk++) {
                        int ii = base - kk;
                        if (ii < 0) ii += Ks[d];
                        idxg[d][kk] = ii;
                    }
                }
                int offx = idxg[0][aa] * KYZ;
                float wx = q * wts[0][aa];
                #pragma unroll
                for (int bb = 0; bb < 5; bb++) {
                    float wab = wx * wts[1][bb];
                    int off = offx + idxg[1][bb] * KZ;
                    #pragma unroll
                    for (int cc = 0; cc < 5; cc++)
                        atomicAdd(&g_grid[off + idxg[2][cc]], wab * wts[2][cc]);
                }
            }
            #pragma unroll
            for (int o = 16; o; o >>= 1) q2c += __shfl_xor_sync(0xffffffffu, q2c, o);
            if (lane == 0) sred[wid] = q2c;
            __syncthreads();
            if (tid == 0) {
                float s = 0.0f;
                #pragma unroll
                for (int w = 0; w < 32; w++) s += sred[w];
                if (s != 0.0f) atomicAdd(&g_q2, (double)s);
            }
        }
        meshbar();   // full mesh ready

        // ---- z-DFT + y-DFT of own plane ----
        if (tid < KYZ) s_plane[tid] = g_grid[m * KYZ + tid];
        __syncthreads();
        if (tid < KYZ) {
            int gy = tid >> 4, mz = tid & 15;
            float fr = 0.0f, fi = 0.0f;
            #pragma unroll
            for (int gz = 0; gz < KZ; gz++) {
                int p = (mz * gz) & (KZ - 1);
                float v = s_plane[(gy << 4) + gz];
                fr = fmaf(v,  s_twc[29 + p], fr);
                fi = fmaf(v, -s_tws[29 + p], fi);
            }
            s_czr[tid] = fr; s_czi[tid] = fi;
        }
        __syncthreads();
        if (tid < KYZ) {
            int my = tid >> 4, mz = tid & 15;
            float fr = 0.0f, fi = 0.0f;
            #pragma unroll
            for (int gy = 0; gy < KY; gy++) {
                float ar = s_czr[(gy << 4) + mz], ai = s_czi[(gy << 4) + mz];
                int p = (my * gy) % KY;
                float c = s_twc[14 + p], s = s_tws[14 + p];
                fr += ar * c + ai * s;
                fi += ai * c - ar * s;
            }
            g_cy[m * KYZ + tid] = make_float2(fr, fi);
        }
        meshbar();   // all planes' cy ready

        // ---- x-DFT + green/B reduce ----
        {
            float contrib = 0.0f;
            if (tid < KYZ) {
                int mx = m, my = tid >> 4, mz = tid & 15;
                float fr = 0.0f, fi = 0.0f;
                #pragma unroll
                for (int gx = 0; gx < KX; gx++) {
                    float2 cv = g_cy[gx * KYZ + tid];
                    int p = (mx * gx) % KX;
                    float c = s_twc[p], s = s_tws[p];
                    fr += cv.x * c + cv.y * s;
                    fi += cv.y * c - cv.x * s;
                }
                int smx = (mx <= (KX - 1) / 2) ? mx : mx - KX;
                int smy = (my <= (KY - 1) / 2) ? my : my - KY;
                int smz = (mz <= (KZ - 1) / 2) ? mz : mz - KZ;
                float fx = (float)smx, fy = (float)smy, fz = (float)smz;
                float mv0 = fx*s_inv[0] + fy*s_inv[1] + fz*s_inv[2];
                float mv1 = fx*s_inv[3] + fy*s_inv[4] + fz*s_inv[5];
                float mv2 = fx*s_inv[6] + fy*s_inv[7] + fz*s_inv[8];
                float m2 = mv0*mv0 + mv1*mv1 + mv2*mv2;
                if (m2 > 0.0f) {
                    const float pi2_over_a2 = (float)(9.869604401089358 / (ALPHAD * ALPHAD));
                    float green = __expf(-pi2_over_a2 * m2) / m2;
                    float B = s_bmod[mx] * s_bmod[14 + my] * s_bmod[29 + mz];
                    contrib = green * B * (fr*fr + fi*fi);
                }
            }
            #pragma unroll
            for (int o = 16; o; o >>= 1) contrib += __shfl_xor_sync(0xffffffffu, contrib, o);
            if (lane == 0) sred[wid] = contrib;
            __syncthreads();
            if (tid == 0) {
                float s = 0.0f;
                #pragma unroll
                for (int w = 0; w < 32; w++) s += sred[w];
                if (s != 0.0f) atomicAdd(&g_erec, (double)s);
            }
        }
        // mesh blocks do NO direct work
    } else {
        // ================= DIRECT BLOCKS (14..147) =================
        float Lx = box[0], Ly = box[4], Lz = box[8];

        // ---- phase A: zero cell counts (block 14), then bin atoms ----
        if (gid == NMESH && tid < NCELL) g_ccnt[tid] = 0;
        dirbar();                        // counts zeroed, visible to all
        {
            int a = (gid - NMESH) * NTHR + tid;   // blocks 14..17 cover all atoms
            if (a < NATOMS) {
                float px = pos[3*a], py = pos[3*a+1], pz = pos[3*a+2];
                int cx = (int)(px * (float)CDIM / Lx); cx = min(CDIM-1, max(0, cx));
                int cy = (int)(py * (float)CDIM / Ly); cy = min(CDIM-1, max(0, cy));
                int cz = (int)(pz * (float)CDIM / Lz); cz = min(CDIM-1, max(0, cz));
                int cid = (cx * CDIM + cy) * CDIM + cz;
                int slot = atomicAdd(&g_ccnt[cid], 1);
                if (slot < CAP) g_cellbuf[cid * CAP + slot] = make_float4(px, py, pz, chg[a]);
            }
        }
        dirbar();                        // all bins visible

        // ---- phase B: warp-level cell-pair tasks (static, no sync) ----
        {
            float acc = 0.0f;
            int gw = (gid - NMESH) * 32 + wid;    // 0..4287
            for (int t = gw; t < NTASK; t += NDWARP) {
                int c = t / 27, k = t - 27 * c;
                int hx = c / 36, rem = c % 36, hy = rem / 6, hz = rem % 6;
                int cx = hx + k / 9 - 1;      if (cx < 0) cx += CDIM; else if (cx >= CDIM) cx -= CDIM;
                int cy = hy + (k / 3) % 3 - 1; if (cy < 0) cy += CDIM; else if (cy >= CDIM) cy -= CDIM;
                int cz = hz + k % 3 - 1;       if (cz < 0) cz += CDIM; else if (cz >= CDIM) cz -= CDIM;
                int n = (cx * CDIM + cy) * CDIM + cz;
                int cnt_h = min(g_ccnt[c], CAP);
                int cnt_n = min(g_ccnt[n], CAP);
                for (int jb = 0; jb < cnt_n; jb += 32) {
                    int j = jb + lane;
                    float4 pj = (j < cnt_n) ? g_cellbuf[n * CAP + j]
                                            : make_float4(1.0e6f, 1.0e6f, 1.0e6f, 0.0f);
                    for (int i = 0; i < cnt_h; i++) {
                        float4 me = g_cellbuf[c * CAP + i];   // uniform: L1 broadcast
                        float dx = fabsf(me.x - pj.x); dx = fminf(dx, Lx - dx);
                        float dy = fabsf(me.y - pj.y); dy = fminf(dy, Ly - dy);
                        float dz = fabsf(me.z - pj.z); dz = fminf(dz, Lz - dz);
                        float r2 = fmaf(dx, dx, fmaf(dy, dy, dz * dz));
                        bool hit = (r2 < CUT2) & (r2 > 0.0f);  // r2==0 <=> self
                        float rinv = rsqrtf(r2);
                        float x = ALPHAF * r2 * rinv;
                        float e = me.w * pj.w * erfc_fast(x) * rinv;
                        acc += hit ? e : 0.0f;                 // FSEL discards junk
                    }
                }
            }
            #pragma unroll
            for (int o = 16; o; o >>= 1) acc += __shfl_xor_sync(0xffffffffu, acc, o);
            if (lane == 0) sred[wid] = acc;
            __syncthreads();
            if (tid == 0) {
                float s = 0.0f;
                #pragma unroll
                for (int w = 0; w < 32; w++) s += sred[w];
                if (s != 0.0f) atomicAdd(&g_edir, (double)s);
            }
        }
    }

    // ================= arrival counter: last block combines + cleans =================
    __syncthreads();
    if (tid == 0) {
        __threadfence();
        unsigned done = atomicAdd(&g_done, 1u);
        if (done == NBLK - 1) {
            __threadfence();             // acquire all blocks' writes
            const double SQRT_PI = 1.7724538509055159;
            double edir  = 0.5 * COULOMB * g_edir;
            double erec  = COULOMB / (2.0 * 3.141592653589793 * g_V) * g_erec;
            double eself = -COULOMB * ALPHAD / SQRT_PI * g_q2;
            out[0] = (float)(edir - (erec + eself));
            // leave-clean for next graph replay (ccnt re-zeroed at replay start)
            g_edir = 0.0; g_erec = 0.0; g_q2 = 0.0;
            __threadfence();
            *(volatile unsigned*)&g_done = 0;
        }
    }
}

extern "C" void kernel_launch(void* const* d_in, const int* in_sizes, int n_in,
                              void* d_out, int out_size) {
    int ip = 0, ic = 1, ib = 2;
    for (int k = 0; k < n_in; k++) {
        if (in_sizes[k] == NATOMS * 3) ip = k;
        else if (in_sizes[k] == NATOMS) ic = k;
        else if (in_sizes[k] == 9)      ib = k;
    }
    const float* pos = (const float*)d_in[ip];
    const float* chg = (const float*)d_in[ic];
    const float* box = (const float*)d_in[ib];
    float* out = (float*)d_out;

    k_all<<<NBLK, NTHR>>>(pos, chg, box, out);
}